// round 6
// baseline (speedup 1.0000x reference)
#include <cuda_runtime.h>
#include <math.h>

#define NN    10000
#define NE    160000
#define HH    128
#define NRBF  32
#define NLAT  64
#define NGR   128
#define CUTR  5.0f
#define EPSF  1e-8f

typedef unsigned long long u64;

// ---------------- device scratch ----------------
__device__ __align__(16) float g_x[NN * HH];
__device__ __align__(16) float g_vec[NN * 3 * HH];
__device__ __align__(16) float g_vmix[NN * 3 * HH];
__device__ __align__(16) float g_vnorm[NN * HH];
__device__ __align__(16) float g_rbf[NE * NRBF];
__device__ __align__(16) float g_dirn[NE * 4];      // (ux,uy,uz,r)
__device__ __align__(16) float g_filt[NE * HH];
__device__ __align__(16) float g_phi[NE * HH];
__device__ __align__(16) float g_pooled[NGR * 65];
// CSR sort
__device__ int g_deg[NN];
__device__ int g_cursor[NN];
__device__ int g_start[NN + 1];
__device__ int g_psrc[NE];
__device__ int g_pdst[NE];

// ---------------- f32x2 packed helpers (bit-exact fp32) ----------------
__device__ __forceinline__ u64 pack2(float a) {
    u64 r; asm("mov.b64 %0, {%1, %1};" : "=l"(r) : "f"(a)); return r;
}
__device__ __forceinline__ void ffma2(u64& d, u64 a, u64 b) {
    asm("fma.rn.f32x2 %0, %1, %2, %0;" : "+l"(d) : "l"(a), "l"(b));
}
__device__ __forceinline__ float red2(u64 v) {
    float lo, hi; asm("mov.b64 {%0, %1}, %2;" : "=f"(lo), "=f"(hi) : "l"(v));
    return lo + hi;
}
__device__ __forceinline__ float4 unpack4(u64 lo, u64 hi) {
    float4 v;
    asm("mov.b64 {%0, %1}, %2;" : "=f"(v.x), "=f"(v.y) : "l"(lo));
    asm("mov.b64 {%0, %1}, %2;" : "=f"(v.z), "=f"(v.w) : "l"(hi));
    return v;
}
__device__ __forceinline__ float silu1(float v) { return v / (1.f + __expf(-v)); }
__device__ __forceinline__ float4 silu4(const float4& v) {
    return make_float4(silu1(v.x), silu1(v.y), silu1(v.z), silu1(v.w));
}

// ---------------- init / zero ----------------
__global__ void k_zero_init() {
    int stride = gridDim.x * blockDim.x;
    int t = blockIdx.x * blockDim.x + threadIdx.x;
    for (int i = t; i < NN * 3 * HH; i += stride) g_vec[i] = 0.f;
    for (int i = t; i < NGR * 65; i += stride) g_pooled[i] = 0.f;
    for (int i = t; i < NN; i += stride) { g_deg[i] = 0; g_cursor[i] = 0; }
}
__global__ void k_init_x(const int* __restrict__ z, const float* __restrict__ emb) {
    int stride = gridDim.x * blockDim.x;
    for (int i = blockIdx.x * blockDim.x + threadIdx.x; i < NN * HH; i += stride) {
        int n = i >> 7, h = i & 127;
        g_x[i] = emb[z[n] * HH + h];
    }
}

// ---------------- CSR build: histogram, scan, scatter ----------------
__global__ void k_hist(const int* __restrict__ ei) {
    int e = blockIdx.x * blockDim.x + threadIdx.x;
    if (e < NE) atomicAdd(&g_deg[ei[NE + e]], 1);
}
__global__ void k_scan() {     // single block, 1024 threads, 10 bins each
    __shared__ int part[1024];
    int t = threadIdx.x;
    int loc[10];
    int s = 0;
#pragma unroll
    for (int i = 0; i < 10; i++) {
        int idx = t * 10 + i;
        int v = (idx < NN) ? g_deg[idx] : 0;
        loc[i] = s; s += v;
    }
    part[t] = s;
    __syncthreads();
    for (int off = 1; off < 1024; off <<= 1) {
        int v = (t >= off) ? part[t - off] : 0;
        __syncthreads();
        part[t] += v;
        __syncthreads();
    }
    int pre = (t == 0) ? 0 : part[t - 1];
#pragma unroll
    for (int i = 0; i < 10; i++) {
        int idx = t * 10 + i;
        if (idx < NN) g_start[idx] = pre + loc[i];
    }
    if (t == 1023) g_start[NN] = part[1023];
}
__global__ void k_scatter(const int* __restrict__ ei) {
    int e = blockIdx.x * blockDim.x + threadIdx.x;
    if (e >= NE) return;
    int s = ei[e], d = ei[NE + e];
    int pos = g_start[d] + atomicAdd(&g_cursor[d], 1);
    g_psrc[pos] = s;
    g_pdst[pos] = d;
}

// ---------------- edge geometry + RBF (sorted order) ----------------
__global__ void k_edgeprep(const float* __restrict__ pos) {
    int e = blockIdx.x * blockDim.x + threadIdx.x;
    if (e >= NE) return;
    int s = g_psrc[e], t = g_pdst[e];
    float dx = pos[t * 3 + 0] - pos[s * 3 + 0];
    float dy = pos[t * 3 + 1] - pos[s * 3 + 1];
    float dz = pos[t * 3 + 2] - pos[s * 3 + 2];
    float r = sqrtf(dx * dx + dy * dy + dz * dz + EPSF);
    float inv = 1.f / r;
    ((float4*)g_dirn)[e] = make_float4(dx * inv, dy * inv, dz * inv, r);

    const float m0 = expf(-CUTR);
    const float step = (1.f - m0) / (NRBF - 1);
    const float bl = (2.f / NRBF) * (1.f - m0);
    const float beta = 1.f / (bl * bl);
    float cutv = (r < CUTR) ? 0.5f * (__cosf(3.14159265358979323846f * r / CUTR) + 1.f) : 0.f;
    float er = __expf(-r);
#pragma unroll
    for (int i = 0; i < NRBF; i++) {
        float m = m0 + step * (float)i;
        float d = er - m;
        g_rbf[e * NRBF + i] = cutv * __expf(-beta * d * d);
    }
}

// ---------------- edge GEMM: filt = rbf@Wrbf; phi = silu((x[src].filt)@W1) ----------------
// k-paired f32x2. smem: WrbfPair 16KB + W1Pair 64KB + per-warp rbf(1KB)+u(4KB) x16
#define EG_THREADS 512
#define SMEM_EDGE ((4096 + 16384 + 16 * 256 + 16 * 1024) * 4)
__global__ void __launch_bounds__(EG_THREADS, 1)
k_edge_gemm(const float* __restrict__ Wrbf, const float* __restrict__ W1) {
    extern __shared__ float sm[];
    float* WrP = sm;              // 16kk x 128c float2
    float* W1P = sm + 4096;       // 64kk x 128c float2
    float* rbfAll = sm + 20480;   // 16 warps x 8 edges x 32
    float* uAll = sm + 24576;     // 16 warps x 8 edges x 128
    int tid = threadIdx.x, warp = tid >> 5, lane = tid & 31;
    for (int i = tid; i < 16 * HH; i += EG_THREADS) {
        int kk = i >> 7, c = i & 127;
        ((float2*)WrP)[i] = make_float2(Wrbf[(2 * kk) * HH + c], Wrbf[(2 * kk + 1) * HH + c]);
    }
    for (int i = tid; i < 64 * HH; i += EG_THREADS) {
        int kk = i >> 7, c = i & 127;
        ((float2*)W1P)[i] = make_float2(W1[(2 * kk) * HH + c], W1[(2 * kk + 1) * HH + c]);
    }
    __syncthreads();
    float* rbfb = rbfAll + warp * 256;
    float* ub = uAll + warp * 1024;
    const ulonglong2* WrP2 = (const ulonglong2*)WrP;
    const ulonglong2* W1P2 = (const ulonglong2*)W1P;

    // lane owns cols {2L, 2L+1, 2L+64, 2L+65}
    int nIter = NE / 8;
    int gstride = gridDim.x * 16;
    for (int g = blockIdx.x * 16 + warp; g < nIter; g += gstride) {
        int e0 = g * 8;
        int srcs[8];
#pragma unroll
        for (int i = 0; i < 8; i++) {
            srcs[i] = g_psrc[e0 + i];
            rbfb[i * 32 + lane] = g_rbf[(e0 + i) * 32 + lane];
        }
        __syncwarp();
        u64 acc[8][4];
#pragma unroll
        for (int i = 0; i < 8; i++) { acc[i][0] = 0; acc[i][1] = 0; acc[i][2] = 0; acc[i][3] = 0; }
#pragma unroll 4
        for (int kk = 0; kk < 16; kk++) {
            ulonglong2 b0 = WrP2[kk * 64 + lane];        // cols 2L,2L+1
            ulonglong2 b1 = WrP2[kk * 64 + 32 + lane];   // cols 2L+64,2L+65
#pragma unroll
            for (int i = 0; i < 8; i++) {
                u64 a = *(const u64*)&rbfb[i * 32 + 2 * kk];
                ffma2(acc[i][0], a, b0.x); ffma2(acc[i][1], a, b0.y);
                ffma2(acc[i][2], a, b1.x); ffma2(acc[i][3], a, b1.y);
            }
        }
        __syncwarp();
#pragma unroll
        for (int i = 0; i < 8; i++) {
            int e = e0 + i;
            float f0 = red2(acc[i][0]), f1 = red2(acc[i][1]);
            float f2 = red2(acc[i][2]), f3 = red2(acc[i][3]);
            ((float2*)&g_filt[(size_t)e * HH])[lane] = make_float2(f0, f1);
            ((float2*)&g_filt[(size_t)e * HH + 64])[lane] = make_float2(f2, f3);
            float2 xa = ((const float2*)&g_x[srcs[i] * HH])[lane];
            float2 xb = ((const float2*)&g_x[srcs[i] * HH + 64])[lane];
            ((float2*)&ub[i * HH])[lane] = make_float2(xa.x * f0, xa.y * f1);
            ((float2*)&ub[i * HH + 64])[lane] = make_float2(xb.x * f2, xb.y * f3);
        }
        __syncwarp();
#pragma unroll
        for (int i = 0; i < 8; i++) { acc[i][0] = 0; acc[i][1] = 0; acc[i][2] = 0; acc[i][3] = 0; }
#pragma unroll 2
        for (int kk = 0; kk < 64; kk++) {
            ulonglong2 b0 = W1P2[kk * 64 + lane];
            ulonglong2 b1 = W1P2[kk * 64 + 32 + lane];
#pragma unroll
            for (int i = 0; i < 8; i++) {
                u64 a = *(const u64*)&ub[i * HH + 2 * kk];
                ffma2(acc[i][0], a, b0.x); ffma2(acc[i][1], a, b0.y);
                ffma2(acc[i][2], a, b1.x); ffma2(acc[i][3], a, b1.y);
            }
        }
#pragma unroll
        for (int i = 0; i < 8; i++) {
            int e = e0 + i;
            float p0 = silu1(red2(acc[i][0])), p1 = silu1(red2(acc[i][1]));
            float p2 = silu1(red2(acc[i][2])), p3 = silu1(red2(acc[i][3]));
            ((float2*)&g_phi[(size_t)e * HH])[lane] = make_float2(p0, p1);
            ((float2*)&g_phi[(size_t)e * HH + 64])[lane] = make_float2(p2, p3);
        }
        __syncwarp();
    }
}

// ---------------- aggregate: warp per node; dx & vec sums + fused x += dx@Wo ----------------
#define SMEM_AGG ((HH * HH + 8 * HH) * 4)
__global__ void k_aggregate(const float* __restrict__ Wo, int has_vmix) {
    extern __shared__ float sm[];
    float* WoSh = sm;                 // 128x128
    float* rowAll = sm + HH * HH;     // 8 warps x 128
    int tid = threadIdx.x, warp = tid >> 5, lane = tid & 31;
    for (int i = tid; i < HH * HH; i += blockDim.x) WoSh[i] = Wo[i];
    __syncthreads();
    float* row = rowAll + warp * HH;
    const ulonglong2* WoSh2 = (const ulonglong2*)WoSh;
    int nwarps = gridDim.x * 8;
    for (int n = blockIdx.x * 8 + warp; n < NN; n += nwarps) {
        int st = g_start[n], en = g_start[n + 1];
        float4 dxa = make_float4(0.f, 0.f, 0.f, 0.f);
        float4 va0 = dxa, va1 = dxa, va2 = dxa;
        for (int e = st; e < en; e++) {
            float4 ph = ((const float4*)&g_phi[(size_t)e * HH])[lane];
            float4 ft = ((const float4*)&g_filt[(size_t)e * HH])[lane];
            float4 dr = ((const float4*)g_dirn)[e];
            dxa.x += ph.x; dxa.y += ph.y; dxa.z += ph.z; dxa.w += ph.w;
            if (has_vmix) {
                int s = g_psrc[e];
                float4 v0 = ((const float4*)&g_vmix[(s * 3 + 0) * HH])[lane];
                float4 v1 = ((const float4*)&g_vmix[(s * 3 + 1) * HH])[lane];
                float4 v2 = ((const float4*)&g_vmix[(s * 3 + 2) * HH])[lane];
                va0.x += v0.x * ft.x + ph.x * dr.x; va0.y += v0.y * ft.y + ph.y * dr.x;
                va0.z += v0.z * ft.z + ph.z * dr.x; va0.w += v0.w * ft.w + ph.w * dr.x;
                va1.x += v1.x * ft.x + ph.x * dr.y; va1.y += v1.y * ft.y + ph.y * dr.y;
                va1.z += v1.z * ft.z + ph.z * dr.y; va1.w += v1.w * ft.w + ph.w * dr.y;
                va2.x += v2.x * ft.x + ph.x * dr.z; va2.y += v2.y * ft.y + ph.y * dr.z;
                va2.z += v2.z * ft.z + ph.z * dr.z; va2.w += v2.w * ft.w + ph.w * dr.z;
            } else {
                va0.x += ph.x * dr.x; va0.y += ph.y * dr.x; va0.z += ph.z * dr.x; va0.w += ph.w * dr.x;
                va1.x += ph.x * dr.y; va1.y += ph.y * dr.y; va1.z += ph.z * dr.y; va1.w += ph.w * dr.y;
                va2.x += ph.x * dr.z; va2.y += ph.y * dr.z; va2.z += ph.z * dr.z; va2.w += ph.w * dr.z;
            }
        }
        // vec += va
        {
            float4* vp0 = (float4*)&g_vec[(n * 3 + 0) * HH];
            float4* vp1 = (float4*)&g_vec[(n * 3 + 1) * HH];
            float4* vp2 = (float4*)&g_vec[(n * 3 + 2) * HH];
            float4 o0 = vp0[lane], o1 = vp1[lane], o2 = vp2[lane];
            o0.x += va0.x; o0.y += va0.y; o0.z += va0.z; o0.w += va0.w;
            o1.x += va1.x; o1.y += va1.y; o1.z += va1.z; o1.w += va1.w;
            o2.x += va2.x; o2.y += va2.y; o2.z += va2.z; o2.w += va2.w;
            vp0[lane] = o0; vp1[lane] = o1; vp2[lane] = o2;
        }
        // x += dx @ Wo
        ((float4*)row)[lane] = dxa;
        __syncwarp();
        u64 alo = 0, ahi = 0;
#pragma unroll 4
        for (int k = 0; k < HH; k++) {
            ulonglong2 b = WoSh2[k * 32 + lane];
            u64 a = pack2(row[k]);
            ffma2(alo, a, b.x); ffma2(ahi, a, b.y);
        }
        float4 accv = unpack4(alo, ahi);
        float4 xo = ((const float4*)&g_x[n * HH])[lane];
        xo.x += accv.x; xo.y += accv.y; xo.z += accv.z; xo.w += accv.w;
        ((float4*)&g_x[n * HH])[lane] = xo;
        __syncwarp();
    }
}

// ---------------- vmix = vec @ Wv (N*3 rows) ----------------
#define SMEM_GEMM ((HH * HH + 8 * 512) * 4)
__global__ void k_vmix(const float* __restrict__ Wv) {
    extern __shared__ float sm[];
    float* Bsh = sm;
    float* rowAll = sm + HH * HH;
    int tid = threadIdx.x, warp = tid >> 5, lane = tid & 31;
    for (int i = tid; i < HH * HH; i += blockDim.x) Bsh[i] = Wv[i];
    __syncthreads();
    float* row = rowAll + warp * 512;
    const ulonglong2* Bsh2 = (const ulonglong2*)Bsh;
    const int rows = NN * 3;
    int nGroups = rows / 4;
    int stride = gridDim.x * 8;
    for (int g = blockIdx.x * 8 + warp; g < nGroups; g += stride) {
        int r0 = g * 4;
#pragma unroll
        for (int i = 0; i < 4; i++)
            ((float4*)row)[i * 32 + lane] = ((const float4*)&g_vec[(r0 + i) * HH])[lane];
        __syncwarp();
        u64 alo[4] = {0, 0, 0, 0}, ahi[4] = {0, 0, 0, 0};
#pragma unroll 4
        for (int k = 0; k < HH; k++) {
            ulonglong2 b = Bsh2[k * 32 + lane];
#pragma unroll
            for (int i = 0; i < 4; i++) {
                u64 a = pack2(row[i * HH + k]);
                ffma2(alo[i], a, b.x); ffma2(ahi[i], a, b.y);
            }
        }
#pragma unroll
        for (int i = 0; i < 4; i++)
            ((float4*)&g_vmix[(r0 + i) * HH])[lane] = unpack4(alo[i], ahi[i]);
        __syncwarp();
    }
}

// ---------------- vnorm = ||vec @ Wvec2||_c ----------------
#define SMEM_VNORM ((HH * HH + 8 * 384) * 4)
__global__ void k_vnorm(const float* __restrict__ Wvec2) {
    extern __shared__ float sm[];
    float* Bsh = sm;
    float* rowAll = sm + HH * HH;
    int tid = threadIdx.x, warp = tid >> 5, lane = tid & 31;
    for (int i = tid; i < HH * HH; i += blockDim.x) Bsh[i] = Wvec2[i];
    __syncthreads();
    float* row = rowAll + warp * 384;
    const ulonglong2* Bsh2 = (const ulonglong2*)Bsh;
    int stride = gridDim.x * 8;
    for (int n = blockIdx.x * 8 + warp; n < NN; n += stride) {
#pragma unroll
        for (int c = 0; c < 3; c++)
            ((float4*)row)[c * 32 + lane] = ((const float4*)&g_vec[(n * 3 + c) * HH])[lane];
        __syncwarp();
        u64 alo[3] = {0, 0, 0}, ahi[3] = {0, 0, 0};
#pragma unroll 4
        for (int k = 0; k < HH; k++) {
            ulonglong2 b = Bsh2[k * 32 + lane];
#pragma unroll
            for (int c = 0; c < 3; c++) {
                u64 a = pack2(row[c * HH + k]);
                ffma2(alo[c], a, b.x); ffma2(ahi[c], a, b.y);
            }
        }
        float4 a0 = unpack4(alo[0], ahi[0]);
        float4 a1 = unpack4(alo[1], ahi[1]);
        float4 a2 = unpack4(alo[2], ahi[2]);
        float4 vn;
        vn.x = sqrtf(a0.x * a0.x + a1.x * a1.x + a2.x * a2.x + EPSF);
        vn.y = sqrtf(a0.y * a0.y + a1.y * a1.y + a2.y * a2.y + EPSF);
        vn.z = sqrtf(a0.z * a0.z + a1.z * a1.z + a2.z * a2.z + EPSF);
        vn.w = sqrtf(a0.w * a0.w + a1.w * a1.w + a2.w * a2.w + EPSF);
        ((float4*)&g_vnorm[n * HH])[lane] = vn;
        __syncwarp();
    }
}

// ---------------- head ----------------
#define SMEM_HEAD ((256 * HH + 8320 + 8 * 256) * 4)
__global__ void k_head(const int* __restrict__ batch,
                       const float* __restrict__ Wa, const float* __restrict__ Wb,
                       const float* __restrict__ ba, const float* __restrict__ bb) {
    extern __shared__ float sm[];
    float* WaSh = sm;
    float* WbSh = WaSh + 256 * HH;
    float* rowAll = WbSh + 8320;
    int tid = threadIdx.x, warp = tid >> 5, lane = tid & 31;
    for (int i = tid; i < 256 * HH; i += blockDim.x) WaSh[i] = Wa[i];
    for (int i = tid; i < 128 * 65; i += blockDim.x) WbSh[i] = Wb[i];
    __syncthreads();
    float* row = rowAll + warp * 256;
    const ulonglong2* WaSh2 = (const ulonglong2*)WaSh;
    int stride = gridDim.x * 8;
    for (int n = blockIdx.x * 8 + warp; n < NN; n += stride) {
        ((float4*)row)[lane] = ((const float4*)&g_x[n * HH])[lane];
        ((float4*)row)[32 + lane] = ((const float4*)&g_vnorm[n * HH])[lane];
        __syncwarp();
        float4 bav = *(const float4*)&ba[lane * 4];
        u64 acclo, acchi;
        asm("mov.b64 %0, {%1, %2};" : "=l"(acclo) : "f"(bav.x), "f"(bav.y));
        asm("mov.b64 %0, {%1, %2};" : "=l"(acchi) : "f"(bav.z), "f"(bav.w));
#pragma unroll 4
        for (int k = 0; k < 256; k++) {
            ulonglong2 b = WaSh2[k * 32 + lane];
            u64 a = pack2(row[k]);
            ffma2(acclo, a, b.x); ffma2(acchi, a, b.y);
        }
        float4 av = silu4(unpack4(acclo, acchi));
        __syncwarp();
        ((float4*)row)[lane] = av;
        __syncwarp();
        int bg = batch[n];
#pragma unroll
        for (int j = 0; j < 3; j++) {
            int col = lane + 32 * j;
            int cc = col < 65 ? col : 64;
            float s = 0.f;
#pragma unroll 4
            for (int k = 0; k < HH; k++) s += row[k] * WbSh[k * 65 + cc];
            if (col < 65) atomicAdd(&g_pooled[bg * 65 + col], s + bb[col]);
        }
        __syncwarp();
    }
}

// ---------------- finalize ----------------
__global__ void k_finalize(float* __restrict__ out) {
    int i = blockIdx.x * blockDim.x + threadIdx.x;
    if (i < NGR * NLAT) {
        int g = i / NLAT, j = i % NLAT;
        out[i] = g_pooled[g * 65 + j];
    } else if (i < NGR * NLAT + NGR) {
        int g = i - NGR * NLAT;
        float v = g_pooled[g * 65 + 64];
        v = fminf(fmaxf(v, -10.f), 2.f);
        out[i] = v;
    }
}

// ---------------- launch ----------------
extern "C" void kernel_launch(void* const* d_in, const int* in_sizes, int n_in,
                              void* d_out, int out_size) {
    const int*   z    = (const int*)d_in[0];
    const float* pos  = (const float*)d_in[1];
    const int*   batch= (const int*)d_in[2];
    const int*   ei   = (const int*)d_in[3];
    const float* emb  = (const float*)d_in[4];
    const float* Wrbf = (const float*)d_in[5];
    const float* W1   = (const float*)d_in[6];
    const float* Wo   = (const float*)d_in[7];
    const float* Wv   = (const float*)d_in[8];
    /* d_in[9] = Wvec1 (unused by reference) */
    const float* Wvec2= (const float*)d_in[10];
    const float* Wa   = (const float*)d_in[11];
    const float* ba   = (const float*)d_in[12];
    const float* Wb   = (const float*)d_in[13];
    const float* bb   = (const float*)d_in[14];
    float* out = (float*)d_out;

    cudaFuncSetAttribute(k_edge_gemm, cudaFuncAttributeMaxDynamicSharedMemorySize, SMEM_EDGE);
    cudaFuncSetAttribute(k_aggregate, cudaFuncAttributeMaxDynamicSharedMemorySize, SMEM_AGG);
    cudaFuncSetAttribute(k_vmix,      cudaFuncAttributeMaxDynamicSharedMemorySize, SMEM_GEMM);
    cudaFuncSetAttribute(k_vnorm,     cudaFuncAttributeMaxDynamicSharedMemorySize, SMEM_VNORM);
    cudaFuncSetAttribute(k_head,      cudaFuncAttributeMaxDynamicSharedMemorySize, SMEM_HEAD);

    k_zero_init<<<256, 256>>>();
    k_hist<<<(NE + 255) / 256, 256>>>(ei);
    k_scan<<<1, 1024>>>();
    k_scatter<<<(NE + 255) / 256, 256>>>(ei);
    k_init_x<<<(NN * HH + 255) / 256, 256>>>(z, emb);
    k_edgeprep<<<(NE + 255) / 256, 256>>>(pos);

    for (int l = 0; l < 2; l++) {
        if (l > 0) k_vmix<<<296, 256, SMEM_GEMM>>>(Wv + l * HH * HH);
        k_edge_gemm<<<148, EG_THREADS, SMEM_EDGE>>>(Wrbf + l * 32 * HH, W1 + l * HH * HH);
        k_aggregate<<<296, 256, SMEM_AGG>>>(Wo + l * HH * HH, l > 0 ? 1 : 0);
    }

    k_vnorm<<<296, 256, SMEM_VNORM>>>(Wvec2);
    k_head<<<148, 256, SMEM_HEAD>>>(batch, Wa, Wb, ba, bb);
    k_finalize<<<(NGR * NLAT + NGR + 255) / 256, 256>>>(out);
}